// round 10
// baseline (speedup 1.0000x reference)
#include <cuda_runtime.h>
#include <cuda_fp16.h>
#include <cstdint>

#define NODES 100000
#define NODES_P 100096            // 782 * 128
#define EDGES 1600000
#define F 256
#define F2 512
#define NSCAN 98                  // ceil(NODES/1024)

// ---------------- scratch (device globals; zero-initialized at load) ---------
__device__ __half g_a2[(size_t)NODES_P * F];   // h in fp16, 51 MB
__device__ __half g_b2[F2 * F];                // combined weight [n][k] fp16
__device__ __half g_hw[(size_t)NODES * F];     // (h@W)*norm fp16, 51 MB
__device__ int   g_deg[NODES];                 // invariant: zero at launch entry
__device__ int   g_off[NODES];
__device__ int   g_cur[NODES];
__device__ int   g_csrc[EDGES];
__device__ int   g_bsum[128];

// ---------------- stream/event fork (created once at static init) -------------
static cudaStream_t g_s1;
static cudaEvent_t  g_ev_fork, g_ev_join;
namespace {
struct StreamInit {
    StreamInit() {
        cudaStreamCreateWithFlags(&g_s1, cudaStreamNonBlocking);
        cudaEventCreateWithFlags(&g_ev_fork, cudaEventDisableTiming);
        cudaEventCreateWithFlags(&g_ev_join, cudaEventDisableTiming);
    }
};
static StreamInit g_stream_init;
}

// ---------------- CSR build --------------------------------------------------
__global__ void k_count(const int* __restrict__ dst) {
    int e = blockIdx.x * blockDim.x + threadIdx.x;
    if (e < EDGES) atomicAdd(&g_deg[dst[e]], 1);
}

__global__ void k_scan1() {
    __shared__ int sm[1024];
    int i = blockIdx.x * 1024 + threadIdx.x;
    int v = (i < NODES) ? g_deg[i] : 0;
    sm[threadIdx.x] = v;
    __syncthreads();
    for (int s = 1; s < 1024; s <<= 1) {
        int t = (threadIdx.x >= s) ? sm[threadIdx.x - s] : 0;
        __syncthreads();
        sm[threadIdx.x] += t;
        __syncthreads();
    }
    if (i < NODES) g_off[i] = sm[threadIdx.x] - v;   // exclusive within block
    if (threadIdx.x == 1023) g_bsum[blockIdx.x] = sm[1023];
}

// merged scan2+scan3: every block redundantly scans the 98 block sums
__global__ void k_scan3b() {
    __shared__ int pre[128];
    int t = threadIdx.x;   // 256 threads
    if (t < 128) pre[t] = (t < NSCAN) ? g_bsum[t] : 0;
    __syncthreads();
#pragma unroll
    for (int s = 1; s < 128; s <<= 1) {
        int u = 0;
        if (t < 128 && t >= s) u = pre[t - s];
        __syncthreads();
        if (t < 128) pre[t] += u;                    // inclusive
        __syncthreads();
    }
    int i = blockIdx.x * blockDim.x + t;
    if (i < NODES) {
        int blk = i >> 10;
        int base = (blk == 0) ? 0 : pre[blk - 1];    // exclusive prefix
        int o = g_off[i] + base;
        g_off[i] = o;
        g_cur[i] = o;
    }
}

__global__ void k_scatter(const int* __restrict__ src, const int* __restrict__ dst) {
    int e = blockIdx.x * blockDim.x + threadIdx.x;
    if (e < EDGES) {
        int p = atomicAdd(&g_cur[dst[e]], 1);
        g_csrc[p] = src[e];
    }
}

// ---------------- fused fp32 -> fp16 operand build ----------------------------
// range [0, HCNT): h rows, 8 floats/thread; range [HCNT, HCNT+F2*F): B elements
#define HCNT (NODES_P * (F / 8))
__global__ void k_conv(const float* __restrict__ h,
                       const float* __restrict__ weight,
                       const float* __restrict__ res_w) {
    int i = blockIdx.x * blockDim.x + threadIdx.x;
    if (i < HCNT) {
        int row = i >> 5;          // 32 threads per row
        int c8  = (i & 31) * 8;
        float4 v0 = make_float4(0.f, 0.f, 0.f, 0.f);
        float4 v1 = v0;
        if (row < NODES) {
            v0 = *(const float4*)&h[(size_t)row * F + c8];
            v1 = *(const float4*)&h[(size_t)row * F + c8 + 4];
        }
        __half2 p0 = __floats2half2_rn(v0.x, v0.y);
        __half2 p1 = __floats2half2_rn(v0.z, v0.w);
        __half2 p2 = __floats2half2_rn(v1.x, v1.y);
        __half2 p3 = __floats2half2_rn(v1.z, v1.w);
        uint4 pk;
        pk.x = *(uint32_t*)&p0; pk.y = *(uint32_t*)&p1;
        pk.z = *(uint32_t*)&p2; pk.w = *(uint32_t*)&p3;
        *(uint4*)&g_a2[(size_t)row * F + c8] = pk;
    } else {
        int j = i - HCNT;
        if (j < F2 * F) {
            int n = j / F, k = j % F;
            float x = (n < F) ? weight[k * F + n] : res_w[(n - F) * F + k];
            g_b2[j] = __float2half_rn(x);
        }
    }
}

// ---------------- HMMA GEMM (mma.sync m16n8k16 fp16) --------------------------
// BM=128, BN=128, BK=64; 256 threads (8 warps: 2M x 4N); 3-stage cp.async pipe.
#define BM 128
#define BN 128
#define BK 64
#define NKC (F / BK)              // 4
#define STAGE_STRIDE 32768        // A(16K) + B(16K) per stage
#define SMEM_DYN (3 * STAGE_STRIDE)   // 96 KB

__device__ __forceinline__ uint32_t smem_u32(const void* p) {
    uint32_t a;
    asm("{ .reg .u64 t; cvta.to.shared.u64 t, %1; cvt.u32.u64 %0, t; }" : "=r"(a) : "l"(p));
    return a;
}

__device__ __forceinline__ uint32_t sw(uint32_t r, uint32_t cg) {
    return r * 128u + ((cg ^ (r & 7u)) << 4);
}

__device__ __forceinline__ void cp16(uint32_t s, const void* g) {
    asm volatile("cp.async.cg.shared.global [%0], [%1], 16;" :: "r"(s), "l"(g));
}

__device__ __forceinline__ void ldsm_x4(uint32_t* r, uint32_t addr) {
    asm volatile("ldmatrix.sync.aligned.m8n8.x4.shared.b16 {%0,%1,%2,%3}, [%4];"
                 : "=r"(r[0]), "=r"(r[1]), "=r"(r[2]), "=r"(r[3]) : "r"(addr));
}

__device__ __forceinline__ void mma_fp16(float* d, const uint32_t* a, uint32_t b0, uint32_t b1) {
    asm volatile(
        "mma.sync.aligned.m16n8k16.row.col.f32.f16.f16.f32 "
        "{%0,%1,%2,%3}, {%4,%5,%6,%7}, {%8,%9}, {%0,%1,%2,%3};"
        : "+f"(d[0]), "+f"(d[1]), "+f"(d[2]), "+f"(d[3])
        : "r"(a[0]), "r"(a[1]), "r"(a[2]), "r"(a[3]), "r"(b0), "r"(b1));
}

__global__ void __launch_bounds__(256, 2) k_gemm_mma(
    const float* __restrict__ norm, const float* __restrict__ res_b,
    float* __restrict__ out)
{
    extern __shared__ char smem[];
    const int tid  = threadIdx.x;
    const int wid  = tid >> 5;
    const int lane = tid & 31;
    const int wm = wid & 1;
    const int wn = wid >> 1;
    const size_t m0 = (size_t)blockIdx.y * BM;
    const int n0 = blockIdx.x * BN;

    const uint32_t sbase = smem_u32(smem);

    float acc[4][4][4];
#pragma unroll
    for (int i = 0; i < 4; i++)
#pragma unroll
        for (int j = 0; j < 4; j++)
#pragma unroll
            for (int q = 0; q < 4; q++) acc[i][j][q] = 0.f;

    const __half* gA = g_a2 + m0 * F;
    const __half* gB = g_b2 + (size_t)n0 * F;

    const int lr = tid >> 3;
    const int lc = tid & 7;

    auto issue = [&](int kc) {
        uint32_t sA = sbase + (kc % 3) * STAGE_STRIDE, sB = sA + 16384;
        const __half* pa = gA + kc * BK + lc * 8;
        const __half* pb = gB + kc * BK + lc * 8;
#pragma unroll
        for (int i = 0; i < 4; i++) {
            int r = lr + i * 32;
            cp16(sA + sw(r, lc), pa + (size_t)r * F);
            cp16(sB + sw(r, lc), pb + (size_t)r * F);
        }
        asm volatile("cp.async.commit_group;");
    };

    issue(0);
    issue(1);

    for (int kc = 0; kc < NKC; kc++) {
        if (kc + 2 < NKC) {
            issue(kc + 2);
            asm volatile("cp.async.wait_group 2;");
        } else if (kc + 1 < NKC) {
            asm volatile("cp.async.wait_group 1;");
        } else {
            asm volatile("cp.async.wait_group 0;");
        }
        __syncthreads();

        uint32_t sA = sbase + (kc % 3) * STAGE_STRIDE, sB = sA + 16384;
#pragma unroll
        for (int ks = 0; ks < 4; ks++) {
            uint32_t a[4][4], bb[2][4];
            {
                int row = wm * 64 + (lane & 7) + ((lane >> 3) & 1) * 8;
                int cg  = ks * 2 + (lane >> 4);
#pragma unroll
                for (int i = 0; i < 4; i++)
                    ldsm_x4(a[i], sA + sw(row + i * 16, cg));
            }
            {
                int row = wn * 32 + (lane & 7) + ((lane >> 4) & 1) * 8;
                int cg  = ks * 2 + ((lane >> 3) & 1);
#pragma unroll
                for (int j = 0; j < 2; j++)
                    ldsm_x4(bb[j], sB + sw(row + j * 16, cg));
            }
#pragma unroll
            for (int i = 0; i < 4; i++)
#pragma unroll
                for (int j = 0; j < 4; j++)
                    mma_fp16(acc[i][j], a[i], bb[j >> 1][(j & 1) * 2], bb[j >> 1][(j & 1) * 2 + 1]);
        }
        __syncthreads();
    }

    // ---- fused epilogue: W half -> g_hw (fp16), residual half -> out (fp32) ----
    const int tq = lane >> 2;
    const int tr = lane & 3;
#pragma unroll
    for (int i = 0; i < 4; i++) {
        size_t row = m0 + wm * 64 + i * 16 + tq;
        bool v0 = row < NODES;
        bool v1 = (row + 8) < NODES;
        float nr0 = v0 ? norm[row] : 0.f;
        float nr1 = v1 ? norm[row + 8] : 0.f;
#pragma unroll
        for (int j = 0; j < 4; j++) {
            int cn = n0 + wn * 32 + j * 8 + tr * 2;
            if (cn < F) {
                if (v0) *(__half2*)&g_hw[row * F + cn] =
                    __floats2half2_rn(acc[i][j][0] * nr0, acc[i][j][1] * nr0);
                if (v1) *(__half2*)&g_hw[(row + 8) * F + cn] =
                    __floats2half2_rn(acc[i][j][2] * nr1, acc[i][j][3] * nr1);
            } else {
                int oc = cn - F;
                float2 rb = *(const float2*)&res_b[oc];
                if (v0) *(float2*)&out[row * F + oc] =
                    make_float2(acc[i][j][0] + rb.x, acc[i][j][1] + rb.y);
                if (v1) *(float2*)&out[(row + 8) * F + oc] =
                    make_float2(acc[i][j][2] + rb.x, acc[i][j][3] + rb.y);
            }
        }
    }
}

// ---------------- aggregation + fused epilogue -------------------------------
__device__ __forceinline__ void acc8(float* a, uint4 v) {
    float2 f0 = __half22float2(*(__half2*)&v.x);
    float2 f1 = __half22float2(*(__half2*)&v.y);
    float2 f2 = __half22float2(*(__half2*)&v.z);
    float2 f3 = __half22float2(*(__half2*)&v.w);
    a[0] += f0.x; a[1] += f0.y; a[2] += f1.x; a[3] += f1.y;
    a[4] += f2.x; a[5] += f2.y; a[6] += f3.x; a[7] += f3.y;
}

__global__ void __launch_bounds__(256) k_agg(
    const float* __restrict__ norm, const float* __restrict__ bias,
    float* __restrict__ out)
{
    int gw   = (blockIdx.x * blockDim.x + threadIdx.x) >> 5;
    int lane = threadIdx.x & 31;
    if (gw >= NODES) return;

    const int start = g_off[gw];
    const int deg   = g_deg[gw];
    const int fo    = lane * 8;

    // hoisted: independent of the gather loop — overlap with its latency
    float nr = norm[gw];
    float4 b0 = *(const float4*)&bias[fo];
    float4 b1 = *(const float4*)&bias[fo + 4];
    float4 r0 = __ldcs((const float4*)&out[(size_t)gw * F + fo]);
    float4 r1 = __ldcs((const float4*)&out[(size_t)gw * F + fo + 4]);

    float a[8];
#pragma unroll
    for (int q = 0; q < 8; q++) a[q] = 0.f;

    int i = 0;
    for (; i + 8 <= deg; i += 8) {
        int s[8];
#pragma unroll
        for (int u = 0; u < 8; u++) s[u] = g_csrc[start + i + u];
        uint4 v[8];
#pragma unroll
        for (int u = 0; u < 8; u++)
            v[u] = *(const uint4*)&g_hw[(size_t)s[u] * F + fo];
#pragma unroll
        for (int u = 0; u < 8; u++) acc8(a, v[u]);
    }
    for (; i + 2 <= deg; i += 2) {
        int s0 = g_csrc[start + i];
        int s1 = g_csrc[start + i + 1];
        uint4 v0 = *(const uint4*)&g_hw[(size_t)s0 * F + fo];
        uint4 v1 = *(const uint4*)&g_hw[(size_t)s1 * F + fo];
        acc8(a, v0);
        acc8(a, v1);
    }
    if (i < deg) {
        int s = g_csrc[start + i];
        acc8(a, *(const uint4*)&g_hw[(size_t)s * F + fo]);
    }

    float4 o0, o1;
    o0.x = fmaxf(a[0] * nr + b0.x + r0.x, 0.f);
    o0.y = fmaxf(a[1] * nr + b0.y + r0.y, 0.f);
    o0.z = fmaxf(a[2] * nr + b0.z + r0.z, 0.f);
    o0.w = fmaxf(a[3] * nr + b0.w + r0.w, 0.f);
    o1.x = fmaxf(a[4] * nr + b1.x + r1.x, 0.f);
    o1.y = fmaxf(a[5] * nr + b1.y + r1.y, 0.f);
    o1.z = fmaxf(a[6] * nr + b1.z + r1.z, 0.f);
    o1.w = fmaxf(a[7] * nr + b1.w + r1.w, 0.f);

    __stcs((float4*)&out[(size_t)gw * F + fo],     o0);
    __stcs((float4*)&out[(size_t)gw * F + fo + 4], o1);

    // restore the g_deg==0 invariant for the next graph replay
    if (lane == 0) g_deg[gw] = 0;
}

// ---------------- launch ------------------------------------------------------
extern "C" void kernel_launch(void* const* d_in, const int* in_sizes, int n_in,
                              void* d_out, int out_size)
{
    const float* h      = (const float*)d_in[0];
    const float* norm   = (const float*)d_in[1];
    const int*   src    = (const int*)d_in[2];
    const int*   dst    = (const int*)d_in[3];
    const float* weight = (const float*)d_in[4];
    const float* bias   = (const float*)d_in[5];
    const float* res_w  = (const float*)d_in[6];
    const float* res_b  = (const float*)d_in[7];
    float* out = (float*)d_out;

    (void)in_sizes; (void)n_in; (void)out_size;

    cudaFuncSetAttribute(k_gemm_mma, cudaFuncAttributeMaxDynamicSharedMemorySize, SMEM_DYN);

    // ---- fork: CSR chain on g_s1, concurrent with conv+GEMM on main stream ----
    cudaEventRecord(g_ev_fork, 0);
    cudaStreamWaitEvent(g_s1, g_ev_fork, 0);

    // CSR build (side stream); g_deg is zero on entry (module init / k_agg tail)
    k_count<<<(EDGES + 255) / 256, 256, 0, g_s1>>>(dst);
    k_scan1<<<NSCAN, 1024, 0, g_s1>>>();
    k_scan3b<<<(NODES + 255) / 256, 256, 0, g_s1>>>();
    k_scatter<<<(EDGES + 255) / 256, 256, 0, g_s1>>>(src, dst);
    cudaEventRecord(g_ev_join, g_s1);

    // fused fp16 operand build + GEMM (main stream)
    int conv_threads = HCNT + F2 * F;
    k_conv<<<(conv_threads + 255) / 256, 256>>>(h, weight, res_w);
    dim3 ggrid(F2 / BN, NODES_P / BM);   // 4 x 782
    k_gemm_mma<<<ggrid, 256, SMEM_DYN>>>(norm, res_b, out);

    // ---- join: agg needs both GEMM (main) and scatter (side) ----
    cudaStreamWaitEvent(0, g_ev_join, 0);
    int nwarp_blocks = (NODES * 32 + 255) / 256;
    k_agg<<<nwarp_blocks, 256>>>(norm, bias, out);
}

// round 11
// speedup vs baseline: 1.1034x; 1.1034x over previous
#include <cuda_runtime.h>
#include <cuda_fp16.h>
#include <cstdint>

#define NODES 100000
#define NODES_P 100096            // 782 * 128
#define EDGES 1600000
#define F 256
#define F2 512
#define NSCAN 98                  // ceil(NODES/1024)

// ---------------- scratch (device globals; zero-initialized at load) ---------
__device__ __half g_a2[(size_t)NODES_P * F];   // h in fp16, 51 MB
__device__ __half g_b2[F2 * F];                // combined weight [n][k] fp16
__device__ __half g_hw[(size_t)NODES * F];     // (h@W)*norm fp16, 51 MB
__device__ int   g_deg[NODES];                 // invariant: zero at launch entry
__device__ int   g_off[NODES];
__device__ int   g_cur[NODES];
__device__ int   g_csrc[EDGES];
__device__ int   g_bsum[128];

// ---------------- stream/event fork (created once at static init) -------------
static cudaStream_t g_s1;
static cudaEvent_t  g_ev_fork, g_ev_join;
namespace {
struct StreamInit {
    StreamInit() {
        cudaStreamCreateWithFlags(&g_s1, cudaStreamNonBlocking);
        cudaEventCreateWithFlags(&g_ev_fork, cudaEventDisableTiming);
        cudaEventCreateWithFlags(&g_ev_join, cudaEventDisableTiming);
    }
};
static StreamInit g_stream_init;
}

// ---------------- CSR build --------------------------------------------------
__global__ void k_count(const int* __restrict__ dst) {
    int e = blockIdx.x * blockDim.x + threadIdx.x;
    if (e < EDGES) atomicAdd(&g_deg[dst[e]], 1);
}

__global__ void k_scan1() {
    __shared__ int sm[1024];
    int i = blockIdx.x * 1024 + threadIdx.x;
    int v = (i < NODES) ? g_deg[i] : 0;
    sm[threadIdx.x] = v;
    __syncthreads();
    for (int s = 1; s < 1024; s <<= 1) {
        int t = (threadIdx.x >= s) ? sm[threadIdx.x - s] : 0;
        __syncthreads();
        sm[threadIdx.x] += t;
        __syncthreads();
    }
    if (i < NODES) g_off[i] = sm[threadIdx.x] - v;   // exclusive within block
    if (threadIdx.x == 1023) g_bsum[blockIdx.x] = sm[1023];
}

// merged scan2+scan3: every block redundantly scans the 98 block sums
__global__ void k_scan3b() {
    __shared__ int pre[128];
    int t = threadIdx.x;   // 256 threads
    if (t < 128) pre[t] = (t < NSCAN) ? g_bsum[t] : 0;
    __syncthreads();
#pragma unroll
    for (int s = 1; s < 128; s <<= 1) {
        int u = 0;
        if (t < 128 && t >= s) u = pre[t - s];
        __syncthreads();
        if (t < 128) pre[t] += u;                    // inclusive
        __syncthreads();
    }
    int i = blockIdx.x * blockDim.x + t;
    if (i < NODES) {
        int blk = i >> 10;
        int base = (blk == 0) ? 0 : pre[blk - 1];    // exclusive prefix
        int o = g_off[i] + base;
        g_off[i] = o;
        g_cur[i] = o;
    }
}

__global__ void k_scatter(const int* __restrict__ src, const int* __restrict__ dst) {
    int e = blockIdx.x * blockDim.x + threadIdx.x;
    if (e < EDGES) {
        int p = atomicAdd(&g_cur[dst[e]], 1);
        g_csrc[p] = src[e];
    }
}

// ---------------- fused fp32 -> fp16 operand build ----------------------------
// range [0, HCNT): h rows, 8 floats/thread; range [HCNT, HCNT+F2*F): B elements
#define HCNT (NODES_P * (F / 8))
__global__ void k_conv(const float* __restrict__ h,
                       const float* __restrict__ weight,
                       const float* __restrict__ res_w) {
    int i = blockIdx.x * blockDim.x + threadIdx.x;
    if (i < HCNT) {
        int row = i >> 5;          // 32 threads per row
        int c8  = (i & 31) * 8;
        float4 v0 = make_float4(0.f, 0.f, 0.f, 0.f);
        float4 v1 = v0;
        if (row < NODES) {
            v0 = *(const float4*)&h[(size_t)row * F + c8];
            v1 = *(const float4*)&h[(size_t)row * F + c8 + 4];
        }
        __half2 p0 = __floats2half2_rn(v0.x, v0.y);
        __half2 p1 = __floats2half2_rn(v0.z, v0.w);
        __half2 p2 = __floats2half2_rn(v1.x, v1.y);
        __half2 p3 = __floats2half2_rn(v1.z, v1.w);
        uint4 pk;
        pk.x = *(uint32_t*)&p0; pk.y = *(uint32_t*)&p1;
        pk.z = *(uint32_t*)&p2; pk.w = *(uint32_t*)&p3;
        *(uint4*)&g_a2[(size_t)row * F + c8] = pk;
    } else {
        int j = i - HCNT;
        if (j < F2 * F) {
            int n = j / F, k = j % F;
            float x = (n < F) ? weight[k * F + n] : res_w[(n - F) * F + k];
            g_b2[j] = __float2half_rn(x);
        }
    }
}

// ---------------- HMMA GEMM (mma.sync m16n8k16 fp16) --------------------------
// BM=128, BN=128, BK=64; 256 threads (8 warps: 2M x 4N); 3-stage cp.async pipe.
#define BM 128
#define BN 128
#define BK 64
#define NKC (F / BK)              // 4
#define STAGE_STRIDE 32768        // A(16K) + B(16K) per stage
#define SMEM_DYN (3 * STAGE_STRIDE)   // 96 KB

__device__ __forceinline__ uint32_t smem_u32(const void* p) {
    uint32_t a;
    asm("{ .reg .u64 t; cvta.to.shared.u64 t, %1; cvt.u32.u64 %0, t; }" : "=r"(a) : "l"(p));
    return a;
}

__device__ __forceinline__ uint32_t sw(uint32_t r, uint32_t cg) {
    return r * 128u + ((cg ^ (r & 7u)) << 4);
}

__device__ __forceinline__ void cp16(uint32_t s, const void* g) {
    asm volatile("cp.async.cg.shared.global [%0], [%1], 16;" :: "r"(s), "l"(g));
}

__device__ __forceinline__ void ldsm_x4(uint32_t* r, uint32_t addr) {
    asm volatile("ldmatrix.sync.aligned.m8n8.x4.shared.b16 {%0,%1,%2,%3}, [%4];"
                 : "=r"(r[0]), "=r"(r[1]), "=r"(r[2]), "=r"(r[3]) : "r"(addr));
}

__device__ __forceinline__ void mma_fp16(float* d, const uint32_t* a, uint32_t b0, uint32_t b1) {
    asm volatile(
        "mma.sync.aligned.m16n8k16.row.col.f32.f16.f16.f32 "
        "{%0,%1,%2,%3}, {%4,%5,%6,%7}, {%8,%9}, {%0,%1,%2,%3};"
        : "+f"(d[0]), "+f"(d[1]), "+f"(d[2]), "+f"(d[3])
        : "r"(a[0]), "r"(a[1]), "r"(a[2]), "r"(a[3]), "r"(b0), "r"(b1));
}

__global__ void __launch_bounds__(256, 2) k_gemm_mma(
    const float* __restrict__ norm, const float* __restrict__ res_b,
    float* __restrict__ out)
{
    extern __shared__ char smem[];
    const int tid  = threadIdx.x;
    const int wid  = tid >> 5;
    const int lane = tid & 31;
    const int wm = wid & 1;
    const int wn = wid >> 1;
    const size_t m0 = (size_t)blockIdx.y * BM;
    const int n0 = blockIdx.x * BN;

    const uint32_t sbase = smem_u32(smem);

    float acc[4][4][4];
#pragma unroll
    for (int i = 0; i < 4; i++)
#pragma unroll
        for (int j = 0; j < 4; j++)
#pragma unroll
            for (int q = 0; q < 4; q++) acc[i][j][q] = 0.f;

    const __half* gA = g_a2 + m0 * F;
    const __half* gB = g_b2 + (size_t)n0 * F;

    const int lr = tid >> 3;
    const int lc = tid & 7;

    auto issue = [&](int kc) {
        uint32_t sA = sbase + (kc % 3) * STAGE_STRIDE, sB = sA + 16384;
        const __half* pa = gA + kc * BK + lc * 8;
        const __half* pb = gB + kc * BK + lc * 8;
#pragma unroll
        for (int i = 0; i < 4; i++) {
            int r = lr + i * 32;
            cp16(sA + sw(r, lc), pa + (size_t)r * F);
            cp16(sB + sw(r, lc), pb + (size_t)r * F);
        }
        asm volatile("cp.async.commit_group;");
    };

    issue(0);
    issue(1);

    for (int kc = 0; kc < NKC; kc++) {
        if (kc + 2 < NKC) {
            issue(kc + 2);
            asm volatile("cp.async.wait_group 2;");
        } else if (kc + 1 < NKC) {
            asm volatile("cp.async.wait_group 1;");
        } else {
            asm volatile("cp.async.wait_group 0;");
        }
        __syncthreads();

        uint32_t sA = sbase + (kc % 3) * STAGE_STRIDE, sB = sA + 16384;
#pragma unroll
        for (int ks = 0; ks < 4; ks++) {
            uint32_t a[4][4], bb[2][4];
            {
                int row = wm * 64 + (lane & 7) + ((lane >> 3) & 1) * 8;
                int cg  = ks * 2 + (lane >> 4);
#pragma unroll
                for (int i = 0; i < 4; i++)
                    ldsm_x4(a[i], sA + sw(row + i * 16, cg));
            }
            {
                int row = wn * 32 + (lane & 7) + ((lane >> 4) & 1) * 8;
                int cg  = ks * 2 + ((lane >> 3) & 1);
#pragma unroll
                for (int j = 0; j < 2; j++)
                    ldsm_x4(bb[j], sB + sw(row + j * 16, cg));
            }
#pragma unroll
            for (int i = 0; i < 4; i++)
#pragma unroll
                for (int j = 0; j < 4; j++)
                    mma_fp16(acc[i][j], a[i], bb[j >> 1][(j & 1) * 2], bb[j >> 1][(j & 1) * 2 + 1]);
        }
        __syncthreads();
    }

    // ---- fused epilogue: W half -> g_hw (fp16), residual half -> out (fp32) ----
    const int tq = lane >> 2;
    const int tr = lane & 3;
#pragma unroll
    for (int i = 0; i < 4; i++) {
        size_t row = m0 + wm * 64 + i * 16 + tq;
        bool v0 = row < NODES;
        bool v1 = (row + 8) < NODES;
        float nr0 = v0 ? norm[row] : 0.f;
        float nr1 = v1 ? norm[row + 8] : 0.f;
#pragma unroll
        for (int j = 0; j < 4; j++) {
            int cn = n0 + wn * 32 + j * 8 + tr * 2;
            if (cn < F) {
                if (v0) *(__half2*)&g_hw[row * F + cn] =
                    __floats2half2_rn(acc[i][j][0] * nr0, acc[i][j][1] * nr0);
                if (v1) *(__half2*)&g_hw[(row + 8) * F + cn] =
                    __floats2half2_rn(acc[i][j][2] * nr1, acc[i][j][3] * nr1);
            } else {
                int oc = cn - F;
                float2 rb = *(const float2*)&res_b[oc];
                if (v0) *(float2*)&out[row * F + oc] =
                    make_float2(acc[i][j][0] + rb.x, acc[i][j][1] + rb.y);
                if (v1) *(float2*)&out[(row + 8) * F + oc] =
                    make_float2(acc[i][j][2] + rb.x, acc[i][j][3] + rb.y);
            }
        }
    }
}

// ---------------- aggregation + fused epilogue (R7/R8 body) -------------------
__device__ __forceinline__ void acc8(float* a, uint4 v) {
    float2 f0 = __half22float2(*(__half2*)&v.x);
    float2 f1 = __half22float2(*(__half2*)&v.y);
    float2 f2 = __half22float2(*(__half2*)&v.z);
    float2 f3 = __half22float2(*(__half2*)&v.w);
    a[0] += f0.x; a[1] += f0.y; a[2] += f1.x; a[3] += f1.y;
    a[4] += f2.x; a[5] += f2.y; a[6] += f3.x; a[7] += f3.y;
}

__global__ void __launch_bounds__(256) k_agg(
    const float* __restrict__ norm, const float* __restrict__ bias,
    float* __restrict__ out)
{
    int gw   = (blockIdx.x * blockDim.x + threadIdx.x) >> 5;
    int lane = threadIdx.x & 31;
    if (gw >= NODES) return;

    const int start = g_off[gw];
    const int deg   = g_deg[gw];
    const int fo    = lane * 8;

    float a[8];
#pragma unroll
    for (int q = 0; q < 8; q++) a[q] = 0.f;

    int i = 0;
    for (; i + 8 <= deg; i += 8) {
        int s[8];
#pragma unroll
        for (int u = 0; u < 8; u++) s[u] = g_csrc[start + i + u];
        uint4 v[8];
#pragma unroll
        for (int u = 0; u < 8; u++)
            v[u] = *(const uint4*)&g_hw[(size_t)s[u] * F + fo];
#pragma unroll
        for (int u = 0; u < 8; u++) acc8(a, v[u]);
    }
    for (; i + 2 <= deg; i += 2) {
        int s0 = g_csrc[start + i];
        int s1 = g_csrc[start + i + 1];
        uint4 v0 = *(const uint4*)&g_hw[(size_t)s0 * F + fo];
        uint4 v1 = *(const uint4*)&g_hw[(size_t)s1 * F + fo];
        acc8(a, v0);
        acc8(a, v1);
    }
    if (i < deg) {
        int s = g_csrc[start + i];
        acc8(a, *(const uint4*)&g_hw[(size_t)s * F + fo]);
    }

    float nr = norm[gw];
    float4 b0 = *(const float4*)&bias[fo];
    float4 b1 = *(const float4*)&bias[fo + 4];
    float4 r0 = *(const float4*)&out[(size_t)gw * F + fo];
    float4 r1 = *(const float4*)&out[(size_t)gw * F + fo + 4];

    float4 o0, o1;
    o0.x = fmaxf(a[0] * nr + b0.x + r0.x, 0.f);
    o0.y = fmaxf(a[1] * nr + b0.y + r0.y, 0.f);
    o0.z = fmaxf(a[2] * nr + b0.z + r0.z, 0.f);
    o0.w = fmaxf(a[3] * nr + b0.w + r0.w, 0.f);
    o1.x = fmaxf(a[4] * nr + b1.x + r1.x, 0.f);
    o1.y = fmaxf(a[5] * nr + b1.y + r1.y, 0.f);
    o1.z = fmaxf(a[6] * nr + b1.z + r1.z, 0.f);
    o1.w = fmaxf(a[7] * nr + b1.w + r1.w, 0.f);

    *(float4*)&out[(size_t)gw * F + fo]     = o0;
    *(float4*)&out[(size_t)gw * F + fo + 4] = o1;

    // restore the g_deg==0 invariant for the next graph replay
    if (lane == 0) g_deg[gw] = 0;
}

// ---------------- launch ------------------------------------------------------
extern "C" void kernel_launch(void* const* d_in, const int* in_sizes, int n_in,
                              void* d_out, int out_size)
{
    const float* h      = (const float*)d_in[0];
    const float* norm   = (const float*)d_in[1];
    const int*   src    = (const int*)d_in[2];
    const int*   dst    = (const int*)d_in[3];
    const float* weight = (const float*)d_in[4];
    const float* bias   = (const float*)d_in[5];
    const float* res_w  = (const float*)d_in[6];
    const float* res_b  = (const float*)d_in[7];
    float* out = (float*)d_out;

    (void)in_sizes; (void)n_in; (void)out_size;

    cudaFuncSetAttribute(k_gemm_mma, cudaFuncAttributeMaxDynamicSharedMemorySize, SMEM_DYN);

    // ---- fork: CSR chain on g_s1, concurrent with conv+GEMM on main stream ----
    cudaEventRecord(g_ev_fork, 0);
    cudaStreamWaitEvent(g_s1, g_ev_fork, 0);

    // CSR build (side stream); g_deg is zero on entry (module init / k_agg tail)
    k_count<<<(EDGES + 255) / 256, 256, 0, g_s1>>>(dst);
    k_scan1<<<NSCAN, 1024, 0, g_s1>>>();
    k_scan3b<<<(NODES + 255) / 256, 256, 0, g_s1>>>();
    k_scatter<<<(EDGES + 255) / 256, 256, 0, g_s1>>>(src, dst);
    cudaEventRecord(g_ev_join, g_s1);

    // fused fp16 operand build + GEMM (main stream)
    int conv_threads = HCNT + F2 * F;
    k_conv<<<(conv_threads + 255) / 256, 256>>>(h, weight, res_w);
    dim3 ggrid(F2 / BN, NODES_P / BM);   // 4 x 782
    k_gemm_mma<<<ggrid, 256, SMEM_DYN>>>(norm, res_b, out);

    // ---- join: agg needs both GEMM (main) and scatter (side) ----
    cudaStreamWaitEvent(0, g_ev_join, 0);
    int nwarp_blocks = (NODES * 32 + 255) / 256;
    k_agg<<<nwarp_blocks, 256>>>(norm, bias, out);
}